// round 1
// baseline (speedup 1.0000x reference)
#include <cuda_runtime.h>

// HyperspectralAttention collapses: per-head channel dim == 1 => softmax over a
// size-1 axis == 1 => attention is identity. The whole module reduces to
//   out = W_proj @ ( illu * ( (0.6*W_v_spec + 0.4*W_v_spat) @ x ) )
// i.e. two 64xNx64 GEMMs (N = B*H*W = 262144) with an elementwise multiply in
// between. Implemented as one fused kernel using packed f32x2 FFMA.

#define TPB 128   // threads per block
#define TP  128   // pixels per block tile

typedef unsigned long long u64;

__device__ __forceinline__ u64 pk2(float lo, float hi) {
    u64 r; asm("mov.b64 %0, {%1,%2};" : "=l"(r) : "f"(lo), "f"(hi)); return r;
}
__device__ __forceinline__ u64 ffma2(u64 a, u64 b, u64 c) {
    u64 d; asm("fma.rn.f32x2 %0, %1, %2, %3;" : "=l"(d) : "l"(a), "l"(b), "l"(c)); return d;
}
__device__ __forceinline__ u64 fmul2(u64 a, u64 b) {
    u64 d; asm("mul.rn.f32x2 %0, %1, %2;" : "=l"(d) : "l"(a), "l"(b)); return d;
}

// Dynamic smem layout:
//   XT  [64][TP]  : X tile during GEMM1, T tile during GEMM2 (aliased)  32KB
//   Wm  [64][64]  : transposed mixed weight  Wm[k][o]                   16KB
//   Wp  [64][64]  : transposed proj  weight  Wp[k][o]                   16KB
// total 64KB -> 3 CTAs / SM.

__global__ __launch_bounds__(TPB) void fused_hsattn(
    const float* __restrict__ x, const float* __restrict__ illu,
    const float* __restrict__ wvspec, const float* __restrict__ wvspat,
    const float* __restrict__ wproj, float* __restrict__ out)
{
    extern __shared__ float smem[];
    float* XT = smem;             // [64][TP]
    float* Wm = smem + 64 * TP;   // [64][64]
    float* Wp = Wm + 64 * 64;     // [64][64]

    const int tid = threadIdx.x;
    const int tp4 = (tid & 15) * 4;   // pixel chunk A start (chunk B at +64)
    const int to8 = (tid >> 4) * 8;   // out-channel base (8 channels/thread)

    const int gbase = blockIdx.x * TP;     // global pixel index base
    const int b  = gbase >> 16;            // / 65536 (H*W)
    const int p0 = gbase & 0xFFFF;
    const size_t base = (size_t)b * (64u << 16);
    const float* xb = x    + base;
    const float* ib = illu + base;
    float*       ob = out  + base;

    // ---- load weights (transposed, mix fused) ----
    for (int i = tid; i < 4096; i += TPB) {
        const int o = i >> 6, c = i & 63;
        Wm[c * 64 + o] = 0.6f * wvspec[i] + 0.4f * wvspat[i];
        Wp[c * 64 + o] = wproj[i];
    }
    // ---- load X tile: 64 rows x TP floats ----
    for (int i = tid; i < 64 * (TP / 4); i += TPB) {
        const int c = i >> 5, j = (i & 31) * 4;
        *(float4*)&XT[c * TP + j] =
            *(const float4*)(xb + ((size_t)c << 16) + p0 + j);
    }
    __syncthreads();

    u64 acc[8][4];
    #pragma unroll
    for (int oj = 0; oj < 8; oj++)
        #pragma unroll
        for (int q = 0; q < 4; q++) acc[oj][q] = 0ull;

    // ---- GEMM1: T = Wmix @ X ----
    #pragma unroll 4
    for (int k = 0; k < 64; k++) {
        const float* wr = &Wm[k * 64 + to8];
        const float4 wa = *(const float4*)wr;
        const float4 wb = *(const float4*)(wr + 4);
        const u64 wd[8] = { pk2(wa.x, wa.x), pk2(wa.y, wa.y), pk2(wa.z, wa.z), pk2(wa.w, wa.w),
                            pk2(wb.x, wb.x), pk2(wb.y, wb.y), pk2(wb.z, wb.z), pk2(wb.w, wb.w) };
        const ulonglong2 xa = *(const ulonglong2*)&XT[k * TP + tp4];
        const ulonglong2 xc = *(const ulonglong2*)&XT[k * TP + 64 + tp4];
        const u64 xp[4] = { xa.x, xa.y, xc.x, xc.y };
        #pragma unroll
        for (int oj = 0; oj < 8; oj++)
            #pragma unroll
            for (int q = 0; q < 4; q++)
                acc[oj][q] = ffma2(wd[oj], xp[q], acc[oj][q]);
    }
    __syncthreads();   // everyone done reading XT before we overwrite with T

    // ---- elementwise illu, write T into XT ----
    #pragma unroll
    for (int oj = 0; oj < 8; oj++) {
        const int o = to8 + oj;
        const size_t ro = ((size_t)o << 16) + p0;
        const ulonglong2 ia = *(const ulonglong2*)(ib + ro + tp4);
        const ulonglong2 ic = *(const ulonglong2*)(ib + ro + 64 + tp4);
        ulonglong2 ta, tc;
        ta.x = fmul2(acc[oj][0], ia.x);
        ta.y = fmul2(acc[oj][1], ia.y);
        tc.x = fmul2(acc[oj][2], ic.x);
        tc.y = fmul2(acc[oj][3], ic.y);
        *(ulonglong2*)&XT[o * TP + tp4]      = ta;
        *(ulonglong2*)&XT[o * TP + 64 + tp4] = tc;
    }
    __syncthreads();   // T fully written before GEMM2 reads it

    #pragma unroll
    for (int oj = 0; oj < 8; oj++)
        #pragma unroll
        for (int q = 0; q < 4; q++) acc[oj][q] = 0ull;

    // ---- GEMM2: Y = Wproj @ T ----
    #pragma unroll 4
    for (int k = 0; k < 64; k++) {
        const float* wr = &Wp[k * 64 + to8];
        const float4 wa = *(const float4*)wr;
        const float4 wb = *(const float4*)(wr + 4);
        const u64 wd[8] = { pk2(wa.x, wa.x), pk2(wa.y, wa.y), pk2(wa.z, wa.z), pk2(wa.w, wa.w),
                            pk2(wb.x, wb.x), pk2(wb.y, wb.y), pk2(wb.z, wb.z), pk2(wb.w, wb.w) };
        const ulonglong2 xa = *(const ulonglong2*)&XT[k * TP + tp4];
        const ulonglong2 xc = *(const ulonglong2*)&XT[k * TP + 64 + tp4];
        const u64 xp[4] = { xa.x, xa.y, xc.x, xc.y };
        #pragma unroll
        for (int oj = 0; oj < 8; oj++)
            #pragma unroll
            for (int q = 0; q < 4; q++)
                acc[oj][q] = ffma2(wd[oj], xp[q], acc[oj][q]);
    }

    // ---- store Y ----
    #pragma unroll
    for (int oj = 0; oj < 8; oj++) {
        const int o = to8 + oj;
        const size_t ro = ((size_t)o << 16) + p0;
        ulonglong2 ya, yc;
        ya.x = acc[oj][0]; ya.y = acc[oj][1];
        yc.x = acc[oj][2]; yc.y = acc[oj][3];
        *(ulonglong2*)(ob + ro + tp4)      = ya;
        *(ulonglong2*)(ob + ro + 64 + tp4) = yc;
    }
}

extern "C" void kernel_launch(void* const* d_in, const int* in_sizes, int n_in,
                              void* d_out, int out_size)
{
    // metadata order: x, illu_feat, w_q_spec, w_k_spec, w_v_spec, w_q_spat,
    //                 w_k_spat, w_v_spat, w_anchor_dw, w_anchor_pw, w_proj,
    //                 temp_spec, temp_spat
    const float* x      = (const float*)d_in[0];
    const float* illu   = (const float*)d_in[1];
    const float* wvspec = (const float*)d_in[4];
    const float* wvspat = (const float*)d_in[7];
    const float* wproj  = (const float*)d_in[10];
    float* out = (float*)d_out;

    const int smem_bytes = (64 * TP + 4096 + 4096) * sizeof(float);  // 64KB
    cudaFuncSetAttribute(fused_hsattn,
                         cudaFuncAttributeMaxDynamicSharedMemorySize, smem_bytes);

    const int n_pix = 4 * 256 * 256;               // B*H*W
    fused_hsattn<<<n_pix / TP, TPB, smem_bytes>>>(x, illu, wvspec, wvspat, wproj, out);
}

// round 3
// speedup vs baseline: 1.7390x; 1.7390x over previous
#include <cuda_runtime.h>
#include <cuda_bf16.h>
#include <cstdint>

// HyperspectralAttention collapses (per-head dim == 1 => softmax == 1) to
//   out = W_proj @ ( illu * ( (0.6*W_v_spec + 0.4*W_v_spat) @ x ) )
// Two 64 x 262144 x 64 GEMMs. tcgen05 is unavailable (harness builds PTX for
// plain sm_103, no 'a' features), so use warp-level mma.sync (HMMA) with a
// bf16 3-way split (Ah*Bh + Ah*Bl + Al*Bh) for fp32-equivalent accuracy.
//
// Orientation: D[o][p] = W[o][c] * X[c][p].
//   A = weights, row-major [o][c] in smem (ldmatrix.x4)
//   B = X, natural [c][p] layout in smem (ldmatrix.x4.trans)
//   D1[o][p] is already B-layout for GEMM2: illu-multiply, re-split, store back.
// Per CTA: 128 threads, 128 pixels; each warp owns a 32-pixel stripe.

#define TPB 128
#define TP  128

// smem byte offsets (dynamic, 64KB total)
#define SM_WMH 0u
#define SM_WML 8192u
#define SM_WPH 16384u
#define SM_WPL 24576u
#define SM_XH  32768u
#define SM_XL  49152u
#define SM_TOTAL 65536

__device__ __forceinline__ uint32_t smem_u32(const void* p) {
    uint32_t a;
    asm("{ .reg .u64 t; cvta.to.shared.u64 t, %1; cvt.u32.u64 %0, t; }"
        : "=r"(a) : "l"(p));
    return a;
}

__device__ __forceinline__ void ldsm4(uint32_t addr, uint32_t r[4]) {
    asm volatile("ldmatrix.sync.aligned.m8n8.x4.shared.b16 {%0,%1,%2,%3}, [%4];"
                 : "=r"(r[0]), "=r"(r[1]), "=r"(r[2]), "=r"(r[3]) : "r"(addr));
}
__device__ __forceinline__ void ldsm4t(uint32_t addr, uint32_t r[4]) {
    asm volatile("ldmatrix.sync.aligned.m8n8.x4.trans.shared.b16 {%0,%1,%2,%3}, [%4];"
                 : "=r"(r[0]), "=r"(r[1]), "=r"(r[2]), "=r"(r[3]) : "r"(addr));
}
__device__ __forceinline__ void mma16816(float c[4], const uint32_t a[4],
                                         uint32_t b0, uint32_t b1) {
    asm volatile("mma.sync.aligned.m16n8k16.row.col.f32.bf16.bf16.f32 "
                 "{%0,%1,%2,%3}, {%4,%5,%6,%7}, {%8,%9}, {%0,%1,%2,%3};"
                 : "+f"(c[0]), "+f"(c[1]), "+f"(c[2]), "+f"(c[3])
                 : "r"(a[0]), "r"(a[1]), "r"(a[2]), "r"(a[3]), "r"(b0), "r"(b1));
}

// split v into bf16 hi + bf16 residual; two values packed per b32
__device__ __forceinline__ void split2(float v0, float v1, uint32_t& hi, uint32_t& lo) {
    __nv_bfloat16 h0 = __float2bfloat16(v0);
    __nv_bfloat16 h1 = __float2bfloat16(v1);
    __nv_bfloat162 hp, lp;
    hp.x = h0; hp.y = h1;
    lp.x = __float2bfloat16(v0 - __bfloat162float(h0));
    lp.y = __float2bfloat16(v1 - __bfloat162float(h1));
    hi = *reinterpret_cast<uint32_t*>(&hp);
    lo = *reinterpret_cast<uint32_t*>(&lp);
}

// One 64x32x64 sub-GEMM for this warp's 32-pixel stripe, 3-way bf16 split.
// acc[mt][nt][4]: mt = o-tile (16 rows), nt = p-tile (8 cols).
__device__ __forceinline__ void gemm64(uint32_t sb, uint32_t whOff, uint32_t wlOff,
                                       int lane, int w, float acc[4][4][4]) {
    const uint32_t arow = ((lane >> 3) & 1) * 8 + (lane & 7);
    const uint32_t asw  = (uint32_t)(lane & 7) << 4;
    #pragma unroll
    for (int kc = 0; kc < 4; kc++) {
        const uint32_t acol = ((uint32_t)(kc * 32 + ((lane >> 4) & 1) * 16)) ^ asw;
        uint32_t ah[4][4], al[4][4];
        #pragma unroll
        for (int mt = 0; mt < 4; mt++) {
            const uint32_t off = (mt * 16 + arow) * 128 + acol;
            ldsm4(sb + whOff + off, ah[mt]);
            ldsm4(sb + wlOff + off, al[mt]);
        }
        const uint32_t brow = kc * 16 + (lane & 15);
        const uint32_t bsw  = (brow & 7) << 4;
        uint32_t bh[2][4], bl[2][4];
        #pragma unroll
        for (int pr = 0; pr < 2; pr++) {
            const uint32_t ncol = w * 32 + pr * 16 + ((lane >> 4) & 1) * 8;
            const uint32_t off  = brow * 256 + (((uint32_t)(2 * ncol)) ^ bsw);
            ldsm4t(sb + SM_XH + off, bh[pr]);
            ldsm4t(sb + SM_XL + off, bl[pr]);
        }
        #pragma unroll
        for (int mt = 0; mt < 4; mt++)
            #pragma unroll
            for (int nt = 0; nt < 4; nt++) {
                const uint32_t b0h = bh[nt >> 1][(nt & 1) * 2];
                const uint32_t b1h = bh[nt >> 1][(nt & 1) * 2 + 1];
                const uint32_t b0l = bl[nt >> 1][(nt & 1) * 2];
                const uint32_t b1l = bl[nt >> 1][(nt & 1) * 2 + 1];
                mma16816(acc[mt][nt], ah[mt], b0h, b1h);
                mma16816(acc[mt][nt], ah[mt], b0l, b1l);
                mma16816(acc[mt][nt], al[mt], b0h, b1h);
            }
    }
}

__global__ __launch_bounds__(TPB, 3) void fused_hmma(
    const float* __restrict__ x, const float* __restrict__ illu,
    const float* __restrict__ wvspec, const float* __restrict__ wvspat,
    const float* __restrict__ wproj, float* __restrict__ out)
{
    extern __shared__ char smem[];
    const uint32_t sb = smem_u32(smem);
    const int tid = threadIdx.x, lane = tid & 31, w = tid >> 5;

    const int gbase = blockIdx.x * TP;
    const int b  = gbase >> 16;
    const int po = gbase & 0xFFFF;
    const size_t base = (size_t)b * 4194304 + (size_t)po;   // b * 64 * 65536
    const float* xb = x    + base;
    const float* ib = illu + base;
    float*       ob = out  + base;

    // ---- weights -> smem bf16 hi/lo, [o][c] rows of 128B, XOR swizzle ----
    for (int i = tid; i < 4096; i += TPB) {
        const int o = i >> 6, c = i & 63;
        const uint32_t off = (uint32_t)(o * 128) +
                             (((uint32_t)(2 * c)) ^ ((uint32_t)(o & 7) << 4));
        const float wm = 0.6f * wvspec[i] + 0.4f * wvspat[i];
        __nv_bfloat16 h = __float2bfloat16(wm);
        *(__nv_bfloat16*)(smem + SM_WMH + off) = h;
        *(__nv_bfloat16*)(smem + SM_WML + off) =
            __float2bfloat16(wm - __bfloat162float(h));
        const float wp = wproj[i];
        h = __float2bfloat16(wp);
        *(__nv_bfloat16*)(smem + SM_WPH + off) = h;
        *(__nv_bfloat16*)(smem + SM_WPL + off) =
            __float2bfloat16(wp - __bfloat162float(h));
    }
    // ---- X tile -> smem bf16 hi/lo, [c][p] rows of 256B, XOR swizzle ----
    for (int i = tid; i < 2048; i += TPB) {
        const int c = i >> 5, p = (i & 31) * 4;
        const float4 v = *(const float4*)(xb + (size_t)c * 65536 + p);
        uint32_t h0, l0, h1, l1;
        split2(v.x, v.y, h0, l0);
        split2(v.z, v.w, h1, l1);
        const uint32_t off = (uint32_t)(c * 256) +
                             (((uint32_t)(2 * p)) ^ ((uint32_t)(c & 7) << 4));
        *(uint2*)(smem + SM_XH + off) = make_uint2(h0, h1);
        *(uint2*)(smem + SM_XL + off) = make_uint2(l0, l1);
    }
    __syncthreads();

    float acc[4][4][4];
    #pragma unroll
    for (int mt = 0; mt < 4; mt++)
        #pragma unroll
        for (int nt = 0; nt < 4; nt++)
            #pragma unroll
            for (int q = 0; q < 4; q++) acc[mt][nt][q] = 0.0f;

    // ---- GEMM1: D1 = Wmix @ X ----
    gemm64(sb, SM_WMH, SM_WML, lane, w, acc);
    __syncwarp();

    // ---- epilogue 1: T = illu * D1, split, back into X buffers ----
    const int g = lane >> 2, t = lane & 3;
    #pragma unroll
    for (int mt = 0; mt < 4; mt++)
        #pragma unroll
        for (int nt = 0; nt < 4; nt++) {
            const int r0 = mt * 16 + g, r1 = r0 + 8;
            const int pp = w * 32 + nt * 8 + 2 * t;
            const float2 i0 = *(const float2*)(ib + (size_t)r0 * 65536 + pp);
            const float2 i1 = *(const float2*)(ib + (size_t)r1 * 65536 + pp);
            uint32_t h, l;
            split2(acc[mt][nt][0] * i0.x, acc[mt][nt][1] * i0.y, h, l);
            const uint32_t off0 = (uint32_t)(r0 * 256) +
                                  (((uint32_t)(2 * pp)) ^ ((uint32_t)(r0 & 7) << 4));
            *(uint32_t*)(smem + SM_XH + off0) = h;
            *(uint32_t*)(smem + SM_XL + off0) = l;
            split2(acc[mt][nt][2] * i1.x, acc[mt][nt][3] * i1.y, h, l);
            const uint32_t off1 = (uint32_t)(r1 * 256) +
                                  (((uint32_t)(2 * pp)) ^ ((uint32_t)(r1 & 7) << 4));
            *(uint32_t*)(smem + SM_XH + off1) = h;
            *(uint32_t*)(smem + SM_XL + off1) = l;
        }
    __syncwarp();

    #pragma unroll
    for (int mt = 0; mt < 4; mt++)
        #pragma unroll
        for (int nt = 0; nt < 4; nt++)
            #pragma unroll
            for (int q = 0; q < 4; q++) acc[mt][nt][q] = 0.0f;

    // ---- GEMM2: Y = Wproj @ T ----
    gemm64(sb, SM_WPH, SM_WPL, lane, w, acc);

    // ---- store Y (8B per lane, lane quads cover 32B sectors) ----
    #pragma unroll
    for (int mt = 0; mt < 4; mt++)
        #pragma unroll
        for (int nt = 0; nt < 4; nt++) {
            const int r0 = mt * 16 + g, r1 = r0 + 8;
            const int pp = w * 32 + nt * 8 + 2 * t;
            *(float2*)(ob + (size_t)r0 * 65536 + pp) =
                make_float2(acc[mt][nt][0], acc[mt][nt][1]);
            *(float2*)(ob + (size_t)r1 * 65536 + pp) =
                make_float2(acc[mt][nt][2], acc[mt][nt][3]);
        }
}

extern "C" void kernel_launch(void* const* d_in, const int* in_sizes, int n_in,
                              void* d_out, int out_size)
{
    const float* x      = (const float*)d_in[0];
    const float* illu   = (const float*)d_in[1];
    const float* wvspec = (const float*)d_in[4];
    const float* wvspat = (const float*)d_in[7];
    const float* wproj  = (const float*)d_in[10];
    float* out = (float*)d_out;

    cudaFuncSetAttribute(fused_hmma, cudaFuncAttributeMaxDynamicSharedMemorySize,
                         SM_TOTAL);
    const int n_pix = 4 * 256 * 256;
    fused_hmma<<<n_pix / TP, TPB, SM_TOTAL>>>(x, illu, wvspec, wvspat, wproj, out);
}